// round 6
// baseline (speedup 1.0000x reference)
#include <cuda_runtime.h>
#include <cuda_bf16.h>

#define D 512
#define MAXC 512
#define MAXN 32768
#define NBLK 64

// Scratch (__device__ globals per allocation-free rule)
__device__ int g_part[NBLK * MAXC];   // per-block class histograms [b][c]
__device__ int g_base[NBLK * MAXC];   // per-block per-class write bases [b][c]
__device__ int g_offsets[MAXC + 1];   // class offsets into g_idx
__device__ int g_idx[MAXN];           // row offsets (i*D), grouped by class

// ---------------------------------------------------------------------------
// Pass 1: per-block private histogram. NO global atomics.
__global__ void hist_kernel(const int* __restrict__ targets, int N) {
    __shared__ int sh[MAXC];
    for (int i = threadIdx.x; i < MAXC; i += blockDim.x) sh[i] = 0;
    __syncthreads();
    for (int i = blockIdx.x * blockDim.x + threadIdx.x; i < N;
         i += gridDim.x * blockDim.x)
        atomicAdd(&sh[targets[i]], 1);
    __syncthreads();
    for (int c = threadIdx.x; c < MAXC; c += blockDim.x)
        g_part[blockIdx.x * MAXC + c] = sh[c];
}

// ---------------------------------------------------------------------------
// Pass 2: per-class cross-block exclusive prefix + class-offset scan.
// One block, 512 threads: thread t owns class t.
__global__ void scan_kernel(float* out) {
    __shared__ int s[MAXC];
    int t = threadIdx.x;  // blockDim.x == MAXC

    // Exclusive prefix over blocks for class t (store intra-class running base)
    int run = 0;
    for (int b = 0; b < NBLK; b++) {
        int v = g_part[b * MAXC + t];
        g_base[b * MAXC + t] = run;   // coalesced across t
        run += v;
    }
    s[t] = run;  // total count of class t
    __syncthreads();

    // Hillis-Steele inclusive scan over 512 class totals
    for (int off = 1; off < MAXC; off <<= 1) {
        int v = s[t];
        int add = (t >= off) ? s[t - off] : 0;
        __syncthreads();
        s[t] = v + add;
        __syncthreads();
    }
    int excl = (t == 0) ? 0 : s[t - 1];
    g_offsets[t] = excl;
    if (t == MAXC - 1) g_offsets[MAXC] = s[MAXC - 1];

    // Fold class offset into the per-block bases
    for (int b = 0; b < NBLK; b++)
        g_base[b * MAXC + t] += excl;

    if (t == 0) out[0] = 0.0f;
}

// ---------------------------------------------------------------------------
// Pass 3: scatter with SHARED-memory cursors only (zero global atomics).
// Must use identical grid/block/stride mapping as hist_kernel.
__global__ void fill_kernel(const int* __restrict__ targets, int N) {
    __shared__ int scur[MAXC];
    for (int c = threadIdx.x; c < MAXC; c += blockDim.x)
        scur[c] = g_base[blockIdx.x * MAXC + c];
    __syncthreads();
    for (int i = blockIdx.x * blockDim.x + threadIdx.x; i < N;
         i += gridDim.x * blockDim.x) {
        int c = targets[i];
        int p = atomicAdd(&scur[c], 1);
        g_idx[p] = i * D;  // pre-scaled row offset
    }
}

__device__ __forceinline__ void f4acc(float4& a, const float4 v) {
    a.x += v.x; a.y += v.y; a.z += v.z; a.w += v.w;
}

// ---------------------------------------------------------------------------
// Pass 4: per-(class, modal) gather-reduce + smooth-L1 epilogue.
// gridDim = (C, 2); blockDim = 512. Thread layout: q = tid&3 row phase,
// g = tid>>2 float4 dim-group (128 groups cover D=512).
__global__ void reduce_kernel(const float* __restrict__ m1,
                              const float* __restrict__ m2,
                              const float* __restrict__ centers,
                              float* __restrict__ out,
                              float inv_nd) {
    int c = blockIdx.x;
    const float* __restrict__ data = blockIdx.y ? m2 : m1;
    int beg = g_offsets[c];
    int end = g_offsets[c + 1];
    int cnt = end - beg;
    if (cnt == 0) return;  // empty classes contribute 0 (never gathered in ref)

    __shared__ int   sidx[1024];
    __shared__ float swarp[16];

    int tid = threadIdx.x;
    int q = tid & 3;
    int g = tid >> 2;

    float4 a0 = make_float4(0.f, 0.f, 0.f, 0.f);
    float4 a1 = make_float4(0.f, 0.f, 0.f, 0.f);

    for (int cs = beg; cs < end; cs += 1024) {
        int m = min(1024, end - cs);
        __syncthreads();
        for (int j = tid; j < m; j += blockDim.x)
            sidx[j] = g_idx[cs + j];
        __syncthreads();

        // 4 rows in flight across q-phases, 2-deep unroll per thread
        int j = q;
        for (; j + 4 < m; j += 8) {
            f4acc(a0, __ldg((const float4*)(data + sidx[j])     + g));
            f4acc(a1, __ldg((const float4*)(data + sidx[j + 4]) + g));
        }
        if (j < m)
            f4acc(a0, __ldg((const float4*)(data + sidx[j]) + g));
    }
    f4acc(a0, a1);

    // Combine the 4 row-phases (lanes 4g..4g+3 are adjacent in-warp)
    #pragma unroll
    for (int o = 1; o <= 2; o <<= 1) {
        a0.x += __shfl_xor_sync(0xffffffff, a0.x, o);
        a0.y += __shfl_xor_sync(0xffffffff, a0.y, o);
        a0.z += __shfl_xor_sync(0xffffffff, a0.z, o);
        a0.w += __shfl_xor_sync(0xffffffff, a0.w, o);
    }

    float v = 0.0f;
    if (q == 0) {
        float inv_cnt = 1.0f / (float)cnt;
        float4 ctr = __ldg((const float4*)(centers + c * D) + g);
        float dx = fabsf(a0.x * inv_cnt - ctr.x);
        float dy = fabsf(a0.y * inv_cnt - ctr.y);
        float dz = fabsf(a0.z * inv_cnt - ctr.z);
        float dw = fabsf(a0.w * inv_cnt - ctr.w);
        float l = ((dx < 1.f) ? 0.5f * dx * dx : dx - 0.5f)
                + ((dy < 1.f) ? 0.5f * dy * dy : dy - 0.5f)
                + ((dz < 1.f) ? 0.5f * dz * dz : dz - 0.5f)
                + ((dw < 1.f) ? 0.5f * dw * dw : dw - 0.5f);
        v = l * (float)cnt;
    }

    // Block reduction (512 threads -> 16 warps -> scalar)
    #pragma unroll
    for (int o = 16; o; o >>= 1) v += __shfl_xor_sync(0xffffffff, v, o);
    if ((tid & 31) == 0) swarp[tid >> 5] = v;
    __syncthreads();
    if (tid < 32) {
        float w = (tid < 16) ? swarp[tid] : 0.0f;
        #pragma unroll
        for (int o = 8; o; o >>= 1) w += __shfl_xor_sync(0xffffffff, w, o);
        if (tid == 0) atomicAdd(out, w * inv_nd);
    }
}

// ---------------------------------------------------------------------------
extern "C" void kernel_launch(void* const* d_in, const int* in_sizes, int n_in,
                              void* d_out, int out_size) {
    const float* m1      = (const float*)d_in[0];  // modal1_inputs [N, 512]
    const float* m2      = (const float*)d_in[1];  // modal2_inputs [N, 512]
    const float* centers = (const float*)d_in[2];  // centers [C, 512]
    const int*   targets = (const int*)d_in[3];    // targets [N]

    int N = in_sizes[3];
    int C = in_sizes[2] / D;
    float* out = (float*)d_out;
    float inv_nd = 1.0f / ((float)N * (float)D);

    hist_kernel<<<NBLK, 512>>>(targets, N);
    scan_kernel<<<1, MAXC>>>(out);
    fill_kernel<<<NBLK, 512>>>(targets, N);
    dim3 grid(C, 2);
    reduce_kernel<<<grid, 512>>>(m1, m2, centers, out, inv_nd);
}

// round 7
// speedup vs baseline: 1.3356x; 1.3356x over previous
#include <cuda_runtime.h>
#include <cuda_bf16.h>

#define D 512
#define MAXC 512
#define MAXN 32768
#define NBLK 64

// Scratch (__device__ globals per allocation-free rule)
__device__ int g_part[NBLK * MAXC];   // per-block class histograms [b][c]
__device__ int g_offsets[MAXC + 1];   // class offsets into g_idx
__device__ int g_idx[MAXN];           // row offsets (i*D), grouped by class

// ---------------------------------------------------------------------------
// Pass 1: per-block private histogram. NO global atomics.
// Grid/block mapping MUST match scanfill_kernel's scatter loop.
__global__ void hist_kernel(const int* __restrict__ targets, int N) {
    __shared__ int sh[MAXC];
    for (int i = threadIdx.x; i < MAXC; i += blockDim.x) sh[i] = 0;
    __syncthreads();
    for (int i = blockIdx.x * blockDim.x + threadIdx.x; i < N;
         i += gridDim.x * blockDim.x)
        atomicAdd(&sh[targets[i]], 1);
    __syncthreads();
    for (int c = threadIdx.x; c < MAXC; c += blockDim.x)
        g_part[blockIdx.x * MAXC + c] = sh[c];
}

// ---------------------------------------------------------------------------
// Pass 2: fused scan + scatter. Each of the 64 blocks redundantly reads the
// full per-block histogram table (L2-hot, 128KB), computes its own per-class
// write base, then scatters its slice of targets via smem cursors only.
__global__ void scanfill_kernel(const int* __restrict__ targets, int N,
                                float* __restrict__ out) {
    __shared__ int s[MAXC];
    __shared__ int scur[MAXC];
    int t = threadIdx.x;   // blockDim.x == MAXC
    int b = blockIdx.x;

    // Cross-block prefix for class t: base within class + class total
    int run = 0, total = 0;
    #pragma unroll
    for (int bb = 0; bb < NBLK; bb++) {
        int v = g_part[bb * MAXC + t];      // coalesced across t
        if (bb < b) run += v;
        total += v;
    }
    s[t] = total;
    __syncthreads();

    // Hillis-Steele inclusive scan over class totals
    for (int off = 1; off < MAXC; off <<= 1) {
        int v = s[t];
        int add = (t >= off) ? s[t - off] : 0;
        __syncthreads();
        s[t] = v + add;
        __syncthreads();
    }
    int excl = (t == 0) ? 0 : s[t - 1];
    scur[t] = excl + run;

    if (b == 0) {
        g_offsets[t] = excl;
        if (t == MAXC - 1) g_offsets[MAXC] = s[MAXC - 1];
        if (t == 0) out[0] = 0.0f;
    }
    __syncthreads();

    // Scatter (identical index mapping as hist_kernel)
    for (int i = b * blockDim.x + t; i < N; i += gridDim.x * blockDim.x) {
        int c = targets[i];
        int p = atomicAdd(&scur[c], 1);
        g_idx[p] = i * D;  // pre-scaled row offset
    }
}

__device__ __forceinline__ void f4acc(float4& a, const float4 v) {
    a.x += v.x; a.y += v.y; a.z += v.z; a.w += v.w;
}

// ---------------------------------------------------------------------------
// Pass 3: per-(class, modal) gather-reduce + smooth-L1 epilogue.
// gridDim = (C, 2); blockDim = 256 with launch_bounds(256,8):
// 8 CTAs/SM * 148 SMs = 1184 >= 790 CTAs -> ENTIRE grid is one resident wave.
// Thread layout: q = tid&1 row-phase, g = tid>>1 float4 column (128 cover D).
__global__ __launch_bounds__(256, 8)
void reduce_kernel(const float* __restrict__ m1,
                   const float* __restrict__ m2,
                   const float* __restrict__ centers,
                   float* __restrict__ out,
                   float inv_nd) {
    int c = blockIdx.x;
    const float* __restrict__ data = blockIdx.y ? m2 : m1;
    int beg = g_offsets[c];
    int end = g_offsets[c + 1];
    int cnt = end - beg;
    if (cnt == 0) return;  // empty classes contribute 0 (never gathered in ref)

    __shared__ int   sidx[1024];
    __shared__ float swarp[8];

    int tid = threadIdx.x;
    int q = tid & 1;
    int g = tid >> 1;

    float4 a0 = make_float4(0.f, 0.f, 0.f, 0.f);
    float4 a1 = make_float4(0.f, 0.f, 0.f, 0.f);

    for (int cs = beg; cs < end; cs += 1024) {
        int m = min(1024, end - cs);
        __syncthreads();
        for (int j = tid; j < m; j += blockDim.x)
            sidx[j] = g_idx[cs + j];
        __syncthreads();

        // 2 row-phases across q, 2 independent load chains per thread
        int j = q;
        for (; j + 2 < m; j += 4) {
            f4acc(a0, __ldg((const float4*)(data + sidx[j])     + g));
            f4acc(a1, __ldg((const float4*)(data + sidx[j + 2]) + g));
        }
        if (j < m)
            f4acc(a0, __ldg((const float4*)(data + sidx[j]) + g));
    }
    f4acc(a0, a1);

    // Combine the 2 row-phases (adjacent lanes share g)
    a0.x += __shfl_xor_sync(0xffffffff, a0.x, 1);
    a0.y += __shfl_xor_sync(0xffffffff, a0.y, 1);
    a0.z += __shfl_xor_sync(0xffffffff, a0.z, 1);
    a0.w += __shfl_xor_sync(0xffffffff, a0.w, 1);

    float v = 0.0f;
    if (q == 0) {
        float inv_cnt = 1.0f / (float)cnt;
        float4 ctr = __ldg((const float4*)(centers + c * D) + g);
        float dx = fabsf(a0.x * inv_cnt - ctr.x);
        float dy = fabsf(a0.y * inv_cnt - ctr.y);
        float dz = fabsf(a0.z * inv_cnt - ctr.z);
        float dw = fabsf(a0.w * inv_cnt - ctr.w);
        float l = ((dx < 1.f) ? 0.5f * dx * dx : dx - 0.5f)
                + ((dy < 1.f) ? 0.5f * dy * dy : dy - 0.5f)
                + ((dz < 1.f) ? 0.5f * dz * dz : dz - 0.5f)
                + ((dw < 1.f) ? 0.5f * dw * dw : dw - 0.5f);
        v = l * (float)cnt;
    }

    // Block reduction (256 threads -> 8 warps -> scalar)
    #pragma unroll
    for (int o = 16; o; o >>= 1) v += __shfl_xor_sync(0xffffffff, v, o);
    if ((tid & 31) == 0) swarp[tid >> 5] = v;
    __syncthreads();
    if (tid < 32) {
        float w = (tid < 8) ? swarp[tid] : 0.0f;
        #pragma unroll
        for (int o = 4; o; o >>= 1) w += __shfl_xor_sync(0xffffffff, w, o);
        if (tid == 0) atomicAdd(out, w * inv_nd);
    }
}

// ---------------------------------------------------------------------------
extern "C" void kernel_launch(void* const* d_in, const int* in_sizes, int n_in,
                              void* d_out, int out_size) {
    const float* m1      = (const float*)d_in[0];  // modal1_inputs [N, 512]
    const float* m2      = (const float*)d_in[1];  // modal2_inputs [N, 512]
    const float* centers = (const float*)d_in[2];  // centers [C, 512]
    const int*   targets = (const int*)d_in[3];    // targets [N]

    int N = in_sizes[3];
    int C = in_sizes[2] / D;
    float* out = (float*)d_out;
    float inv_nd = 1.0f / ((float)N * (float)D);

    hist_kernel<<<NBLK, 512>>>(targets, N);
    scanfill_kernel<<<NBLK, MAXC>>>(targets, N, out);
    dim3 grid(C, 2);
    reduce_kernel<<<grid, 256>>>(m1, m2, centers, out, inv_nd);
}